// round 11
// baseline (speedup 1.0000x reference)
#include <cuda_runtime.h>
#include <cstdint>

// Problem constants (fixed by the reference)
#define HW_TOTAL (512 * 512)                  // 262144 pixels per batch image
#define BATCH 32
#define PSAMP 8192
#define NSAMP (BATCH * PSAMP)                 // 262144 samples
#define GPB 1024                              // 256-px groups per batch
#define LUTN 2048                             // rank->group LUT entries (gran 128)
#define EPS_F 1e-5f

#define NBLK 512                              // total blocks (256 prod + 256 cons)
#define NTHR 512

// -------- device scratch (static globals: no runtime allocation) --------
__device__ __align__(256) unsigned char g_bytes[(size_t)BATCH * GPB * 32]; // 1 MB packed mask
__device__ __align__(16)  unsigned short g_grpCnt[BATCH * GPB];            // 64 KB group counts
__device__ __align__(16)  int            g_grpOff[BATCH * GPB];            // 128 KB group offsets
__device__ __align__(16)  unsigned short g_lut[BATCH * LUTN];              // 128 KB rank->group
__device__ int      g_validNum[BATCH];
__device__ unsigned g_prodDone[BATCH];
__device__ unsigned g_ready[BATCH];
__device__ double   g_sum1, g_sum2;
__device__ int      g_cnt1, g_cnt2;
__device__ unsigned g_done;

// ======== kernel 0: reset flags + accumulators ========
__global__ void k_reset() {
    int t = threadIdx.x;
    if (t < BATCH) { g_prodDone[t] = 0u; g_ready[t] = 0u; }
    if (t == 0) { g_sum1 = 0.0; g_sum2 = 0.0; g_cnt1 = 0; g_cnt2 = 0; g_done = 0u; }
}

// ======== select: rank -> pixel (smem offsets/LUT, L2 bit-words) ========
__device__ __forceinline__ int rank_select(int j, const int* sgoff,
                                           const unsigned short* slut,
                                           const unsigned char* bytesBatch) {
    int g = slut[j >> 7];
    while (sgoff[g + 1] <= j) g++;
    int r = j - sgoff[g];

    const ulonglong2* bp =
        reinterpret_cast<const ulonglong2*>(bytesBatch + (size_t)g * 32);
    ulonglong2 q0 = __ldcg(bp + 0);
    ulonglong2 q1 = __ldcg(bp + 1);

    unsigned long long w = q0.x; int wsel = 0;
    int q = __popcll(q0.x);
    if (r >= q) { r -= q; q = __popcll(q0.y);
        if (r >= q) { r -= q; q = __popcll(q1.x);
            if (r >= q) { r -= q; w = q1.y; wsel = 3; }
            else        {         w = q1.x; wsel = 2; } }
        else        {         w = q0.y; wsel = 1; } }
    unsigned lo = (unsigned)w; int pl = __popc(lo);
    int bit = (r < pl) ? (int)__fns(lo, 0, r + 1)
                       : 32 + (int)__fns((unsigned)(w >> 32), 0, r - pl + 1);
    return g * 256 + wsel * 64 + bit;
}

// ======== fused persistent kernel: producers (even bid) + consumers (odd) ===
__global__ void __launch_bounds__(NTHR, 4) k_fused(const float* __restrict__ d3,
                                                   const float* __restrict__ dp,
                                                   const int* __restrict__ mask,
                                                   const int* __restrict__ s1,
                                                   const int* __restrict__ s2,
                                                   float* __restrict__ out) {
    const int t = threadIdx.x, lane = t & 31, wid = t >> 5;

    if ((blockIdx.x & 1) == 0) {
        // ================= PRODUCER =================
        const int p = blockIdx.x >> 1;            // 0..255
        const int b = p >> 3;                     // 8 producers per batch
        const int r = p & 7;                      // region within batch
        const size_t pxBase = (size_t)b * HW_TOTAL + (size_t)r * 32768 +
                              (size_t)t * 64;

        // 64 px/thread: 16 int4 loads -> 4 u16 mask words -> one u64 store
        const int4* mp = reinterpret_cast<const int4*>(mask + pxBase);
        unsigned long long m64 = 0ull;
        int c = 0;
        #pragma unroll
        for (int k = 0; k < 4; k++) {
            int4 v0 = __ldcs(mp + k * 4 + 0);
            int4 v1 = __ldcs(mp + k * 4 + 1);
            int4 v2 = __ldcs(mp + k * 4 + 2);
            int4 v3 = __ldcs(mp + k * 4 + 3);
            unsigned m16 =
                  (unsigned)(v0.x != 0)       | (unsigned)(v0.y != 0) << 1
                | (unsigned)(v0.z != 0) << 2  | (unsigned)(v0.w != 0) << 3
                | (unsigned)(v1.x != 0) << 4  | (unsigned)(v1.y != 0) << 5
                | (unsigned)(v1.z != 0) << 6  | (unsigned)(v1.w != 0) << 7
                | (unsigned)(v2.x != 0) << 8  | (unsigned)(v2.y != 0) << 9
                | (unsigned)(v2.z != 0) << 10 | (unsigned)(v2.w != 0) << 11
                | (unsigned)(v3.x != 0) << 12 | (unsigned)(v3.y != 0) << 13
                | (unsigned)(v3.z != 0) << 14 | (unsigned)(v3.w != 0) << 15;
            m64 |= (unsigned long long)m16 << (k * 16);
            c += __popc(m16);
        }
        *reinterpret_cast<unsigned long long*>(
            g_bytes + pxBase / 8) = m64;          // 8B-aligned

        // 4 threads = one 256-px group
        const unsigned segMask = 0xFu << (lane & ~3);
        const int gsum = __reduce_add_sync(segMask, c);
        if ((lane & 3) == 0)
            g_grpCnt[b * GPB + r * 128 + (t >> 2)] = (unsigned short)gsum;

        __syncthreads();                          // all block stores issued
        __shared__ unsigned sIsLast;
        __threadfence();                          // make visible before count
        if (t == 0) sIsLast = atomicAdd(&g_prodDone[b], 1u);
        __syncthreads();
        if (sIsLast != 7u) return;                // not the last producer

        // ---- last producer of batch b: scan 1024 group counts + LUT ----
        __shared__ int wtot[16];
        __shared__ int wexc[16];
        __shared__ int svn;
        ushort2 gc = reinterpret_cast<const ushort2*>(g_grpCnt + b * GPB)[t];
        const int c0 = gc.x, c1 = gc.y;
        const int s2c = c0 + c1;
        int inc = s2c;
        #pragma unroll
        for (int o = 1; o < 32; o <<= 1) {
            int v = __shfl_up_sync(0xFFFFFFFFu, inc, o);
            if (lane >= o) inc += v;
        }
        if (lane == 31) wtot[wid] = inc;
        __syncthreads();
        if (wid == 0 && lane < 16) {
            int v = wtot[lane];
            int i16 = v;
            #pragma unroll
            for (int o = 1; o < 16; o <<= 1) {
                int u = __shfl_up_sync(0xFFFFu, i16, o);
                if (lane >= o) i16 += u;
            }
            wexc[lane] = i16 - v;
            if (lane == 15) { svn = i16; g_validNum[b] = i16; }
        }
        __syncthreads();

        const int exc = wexc[wid] + (inc - s2c);
        int2 go2; go2.x = exc; go2.y = exc + c0;
        int* go = g_grpOff + b * GPB;
        reinterpret_cast<int2*>(go)[t] = go2;
        __syncthreads();

        unsigned short* lut = g_lut + b * LUTN;
        const int vn = svn;
        #pragma unroll
        for (int k = 0; k < 2; k++) {
            int g = t * 2 + k;
            int start = (k == 0) ? go2.x : go2.y;
            int end = (g == GPB - 1) ? vn : go[g + 1];
            for (int kk = (start + 127) >> 7; (kk << 7) < end; kk++)
                lut[kk] = (unsigned short)g;
        }

        __syncthreads();
        __threadfence();
        if (t == 0) atomicExch(&g_ready[b], 1u);  // publish
        return;
    }

    // ================= CONSUMER =================
    const int cblk = blockIdx.x >> 1;             // 0..255
    const int b = cblk >> 3;                      // 8 consumers per batch
    const int iBase = b * PSAMP + (cblk & 7) * 1024;

    __shared__ __align__(16) int            sgoff[GPB + 4];
    __shared__ __align__(16) unsigned short slut[LUTN];
    __shared__ float sf1[16], sf2[16];
    __shared__ int   si1[16], si2[16];

    // wait for my batch's structure
    if (t == 0) {
        while (atomicAdd(&g_ready[b], 0u) == 0u) __nanosleep(200);
    }
    __syncthreads();
    __threadfence();                              // acquire published data

    // prologue: 8 KB L2 -> smem
    if (t < 256) {
        reinterpret_cast<uint4*>(sgoff)[t] =
            reinterpret_cast<const uint4*>(g_grpOff + b * GPB)[t];
    } else {
        reinterpret_cast<uint4*>(slut)[t - 256] =
            reinterpret_cast<const uint4*>(g_lut + b * LUTN)[t - 256];
    }
    if (t == 0) sgoff[GPB] = g_validNum[b];
    __syncthreads();

    const int vn = sgoff[GPB];
    const size_t bo = (size_t)b * HW_TOTAL;
    const unsigned char* bytesBatch = g_bytes + (size_t)b * 32768;

    // 2 samples/thread
    const int i0 = iBase + t;
    const int i1 = iBase + t + 512;
    const int j1a = s1[i0] % vn, j2a = s2[i0] % vn;
    const int j1b = s1[i1] % vn, j2b = s2[i1] % vn;

    const int p1a = rank_select(j1a, sgoff, slut, bytesBatch);
    const int p2a = rank_select(j2a, sgoff, slut, bytesBatch);
    const int p1b = rank_select(j1b, sgoff, slut, bytesBatch);
    const int p2b = rank_select(j2b, sgoff, slut, bytesBatch);

    const float a_a = __ldcg(d3 + bo + p1a);
    const float b_a = __ldcg(d3 + bo + p2a);
    const float a_b = __ldcg(d3 + bo + p1b);
    const float b_b = __ldcg(d3 + bo + p2b);
    const float df_a = __ldcg(dp + bo + p1a) - __ldcg(dp + bo + p2a);
    const float df_b = __ldcg(dp + bo + p1b) - __ldcg(dp + bo + p2b);

    float ls1 = 0.f, ls2 = 0.f;
    int lc1 = 0, lc2 = 0;
    if (a_a > b_a + EPS_F) { ls1 += fmaxf(-df_a, 0.f); lc1++; }
    if (a_a < b_a - EPS_F) { ls2 += fmaxf(df_a, 0.f);  lc2++; }
    if (a_b > b_b + EPS_F) { ls1 += fmaxf(-df_b, 0.f); lc1++; }
    if (a_b < b_b - EPS_F) { ls2 += fmaxf(df_b, 0.f);  lc2++; }

    #pragma unroll
    for (int o = 16; o; o >>= 1) {
        ls1 += __shfl_down_sync(0xFFFFFFFFu, ls1, o);
        ls2 += __shfl_down_sync(0xFFFFFFFFu, ls2, o);
        lc1 += __shfl_down_sync(0xFFFFFFFFu, lc1, o);
        lc2 += __shfl_down_sync(0xFFFFFFFFu, lc2, o);
    }
    if (lane == 0) { sf1[wid] = ls1; sf2[wid] = ls2; si1[wid] = lc1; si2[wid] = lc2; }
    __syncthreads();
    if (wid == 0) {
        float v1 = (lane < 16) ? sf1[lane] : 0.f;
        float v2 = (lane < 16) ? sf2[lane] : 0.f;
        int   i1r = (lane < 16) ? si1[lane] : 0;
        int   i2r = (lane < 16) ? si2[lane] : 0;
        #pragma unroll
        for (int o = 8; o; o >>= 1) {
            v1 += __shfl_down_sync(0xFFFFFFFFu, v1, o);
            v2 += __shfl_down_sync(0xFFFFFFFFu, v2, o);
            i1r += __shfl_down_sync(0xFFFFFFFFu, i1r, o);
            i2r += __shfl_down_sync(0xFFFFFFFFu, i2r, o);
        }
        if (lane == 0) {
            atomicAdd(&g_sum1, (double)v1);
            atomicAdd(&g_sum2, (double)v2);
            atomicAdd(&g_cnt1, i1r);
            atomicAdd(&g_cnt2, i2r);
        }
    }

    // last consumer block finalizes
    __threadfence();
    __syncthreads();
    if (t == 0) {
        if (atomicAdd(&g_done, 1u) == (NBLK / 2) - 1u) {
            double a1 = *(volatile double*)&g_sum1;
            double a2 = *(volatile double*)&g_sum2;
            int    n1 = *(volatile int*)&g_cnt1;
            int    n2 = *(volatile int*)&g_cnt2;
            out[0] = 0.5f * (float)(a1 / (double)n1 + a2 / (double)n2);
        }
    }
}

extern "C" void kernel_launch(void* const* d_in, const int* in_sizes, int n_in,
                              void* d_out, int out_size) {
    const float* d3   = (const float*)d_in[0];   // depth_3dmm
    const float* dp   = (const float*)d_in[1];   // depth_pigan
    const int*   mask = (const int*)d_in[2];
    const int*   s1   = (const int*)d_in[3];
    const int*   s2   = (const int*)d_in[4];

    k_reset<<<1, 64>>>();
    k_fused<<<NBLK, NTHR>>>(d3, dp, mask, s1, s2, (float*)d_out);
}

// round 12
// speedup vs baseline: 1.7980x; 1.7980x over previous
#include <cuda_runtime.h>
#include <cstdint>

// Problem constants (fixed by the reference)
#define HW_TOTAL (512 * 512)                  // 262144 pixels per batch image
#define BATCH 32
#define PSAMP 8192
#define NSAMP (BATCH * PSAMP)                 // 262144 samples
#define GPB 1024                              // 256-px groups per batch
#define LUTN 2048                             // rank->group LUT entries (gran 128)
#define EPS_F 1e-5f

#define CNT_BLOCKS 512                        // persistent: 2 tiles of 8192 px each
#define SMP_BLOCKS (NSAMP / 512)              // 512 (512 samples per block)

// -------- device scratch (static globals: no runtime allocation) --------
__device__ __align__(256) unsigned char g_bytes[(size_t)BATCH * GPB * 32]; // 1 MB packed mask
__device__ __align__(16)  unsigned short g_grpCnt[BATCH * GPB];            // 64 KB group counts
__device__ __align__(16)  int            g_grpOff[BATCH * GPB];            // 128 KB group offsets
__device__ __align__(16)  unsigned short g_lut[BATCH * LUTN];              // 128 KB rank->group
__device__ int      g_validNum[BATCH];
__device__ double   g_sum1, g_sum2;
__device__ int      g_cnt1, g_cnt2;
__device__ unsigned g_done2;                  // zero-init; self-resetting

// ======== kernel 1: mask -> bitmask + group counts (1 wave, 2 tiles/block) ==
__global__ void __launch_bounds__(512) k_count(const int* __restrict__ mask) {
    const int t = threadIdx.x, lane = t & 31;

    #pragma unroll 1
    for (int tile = 0; tile < 2; tile++) {
        const size_t basePx = (size_t)blockIdx.x * 16384 +
                              (size_t)tile * 8192 + (size_t)t * 16;
        const int4* p = reinterpret_cast<const int4*>(mask + basePx);
        int4 v0 = __ldcs(p + 0);
        int4 v1 = __ldcs(p + 1);
        int4 v2 = __ldcs(p + 2);
        int4 v3 = __ldcs(p + 3);

        unsigned m16 =
              (unsigned)(v0.x != 0)       | (unsigned)(v0.y != 0) << 1
            | (unsigned)(v0.z != 0) << 2  | (unsigned)(v0.w != 0) << 3
            | (unsigned)(v1.x != 0) << 4  | (unsigned)(v1.y != 0) << 5
            | (unsigned)(v1.z != 0) << 6  | (unsigned)(v1.w != 0) << 7
            | (unsigned)(v2.x != 0) << 8  | (unsigned)(v2.y != 0) << 9
            | (unsigned)(v2.z != 0) << 10 | (unsigned)(v2.w != 0) << 11
            | (unsigned)(v3.x != 0) << 12 | (unsigned)(v3.y != 0) << 13
            | (unsigned)(v3.z != 0) << 14 | (unsigned)(v3.w != 0) << 15;

        reinterpret_cast<unsigned short*>(g_bytes)[blockIdx.x * 1024 +
                                                   tile * 512 + t] =
            (unsigned short)m16;

        const int c = __popc(m16);
        const unsigned hm = (lane < 16) ? 0x0000FFFFu : 0xFFFF0000u;
        const int gsum = __reduce_add_sync(hm, c);
        if ((lane & 15) == 0)
            g_grpCnt[blockIdx.x * 64 + tile * 32 + (t >> 4)] =
                (unsigned short)gsum;
    }
}

// ======== kernel 2: per-batch 1024-group scan + grpOff + LUT ========
__global__ void __launch_bounds__(256) k_prep() {
    const int b = blockIdx.x;
    const int t = threadIdx.x, lane = t & 31, wid = t >> 5;

    __shared__ int wtot[8];
    __shared__ int wexc[8];
    __shared__ int svn;

    ushort4 gc = reinterpret_cast<const ushort4*>(g_grpCnt + b * GPB)[t];
    const int c0 = gc.x, c1 = gc.y, c2 = gc.z, c3 = gc.w;
    const int s4 = c0 + c1 + c2 + c3;

    int inc = s4;
    #pragma unroll
    for (int o = 1; o < 32; o <<= 1) {
        int v = __shfl_up_sync(0xFFFFFFFFu, inc, o);
        if (lane >= o) inc += v;
    }
    if (lane == 31) wtot[wid] = inc;
    __syncthreads();
    if (wid == 0 && lane < 8) {
        int v = wtot[lane];
        int i8 = v;
        #pragma unroll
        for (int o = 1; o < 8; o <<= 1) {
            int u = __shfl_up_sync(0xFFu, i8, o);
            if (lane >= o) i8 += u;
        }
        wexc[lane] = i8 - v;
        if (lane == 7) { svn = i8; g_validNum[b] = i8; }
    }
    __syncthreads();

    const int exc = wexc[wid] + (inc - s4);
    int4 go4;
    go4.x = exc;
    go4.y = exc + c0;
    go4.z = exc + c0 + c1;
    go4.w = exc + c0 + c1 + c2;
    int* go = g_grpOff + b * GPB;
    reinterpret_cast<int4*>(go)[t] = go4;
    __syncthreads();

    unsigned short* lut = g_lut + b * LUTN;
    const int vn = svn;
    #pragma unroll
    for (int k = 0; k < 4; k++) {
        int g = t * 4 + k;
        int start = (&go4.x)[k];
        int end = (g == GPB - 1) ? vn : go[g + 1];
        for (int kk = (start + 127) >> 7; (kk << 7) < end; kk++)
            lut[kk] = (unsigned short)g;
    }

    if (b == 0 && t == 0) { g_sum1 = 0.0; g_sum2 = 0.0; g_cnt1 = 0; g_cnt2 = 0; }
}

// ======== select: rank -> pixel (smem offsets/LUT, L1-cached bit-words) ====
__device__ __forceinline__ int rank_select(int j, const int* sgoff,
                                           const unsigned short* slut,
                                           const unsigned char* bytesBatch) {
    int g = slut[j >> 7];
    while (sgoff[g + 1] <= j) g++;
    int r = j - sgoff[g];

    const ulonglong2* bp =
        reinterpret_cast<const ulonglong2*>(bytesBatch + (size_t)g * 32);
    ulonglong2 q0 = bp[0];          // default (L1-cached) loads
    ulonglong2 q1 = bp[1];

    unsigned long long w = q0.x; int wsel = 0;
    int q = __popcll(q0.x);
    if (r >= q) { r -= q; q = __popcll(q0.y);
        if (r >= q) { r -= q; q = __popcll(q1.x);
            if (r >= q) { r -= q; w = q1.y; wsel = 3; }
            else        {         w = q1.x; wsel = 2; } }
        else        {         w = q0.y; wsel = 1; } }
    unsigned lo = (unsigned)w; int pl = __popc(lo);
    int bit = (r < pl) ? (int)__fns(lo, 0, r + 1)
                       : 32 + (int)__fns((unsigned)(w >> 32), 0, r - pl + 1);
    return g * 256 + wsel * 64 + bit;
}

// ======== kernel 3: sample gather + reduce (1 sample/thread, 512 thr) ======
__global__ void __launch_bounds__(512) k_sample(const float* __restrict__ d3,
                                                const float* __restrict__ dp,
                                                const int* __restrict__ s1,
                                                const int* __restrict__ s2,
                                                float* __restrict__ out) {
    const int t = threadIdx.x, lane = t & 31, wid = t >> 5;
    const int b = blockIdx.x >> 4;                       // 16 blocks per batch
    const int i = b * PSAMP + (blockIdx.x & 15) * 512 + t;

    // early independent loads (overlap with prologue)
    const int sv1 = __ldcg(s1 + i);
    const int sv2 = __ldcg(s2 + i);
    const int vn  = __ldg(&g_validNum[b]);

    __shared__ __align__(16) int            sgoff[GPB + 4];  // 4 KB + pad
    __shared__ __align__(16) unsigned short slut[LUTN];      // 4 KB
    __shared__ float sf1[16], sf2[16];
    __shared__ int   si1[16], si2[16];

    // prologue: 8 KB L2 -> smem (one 16B op per thread)
    if (t < 256) {
        reinterpret_cast<uint4*>(sgoff)[t] =
            reinterpret_cast<const uint4*>(g_grpOff + b * GPB)[t];
    } else {
        reinterpret_cast<uint4*>(slut)[t - 256] =
            reinterpret_cast<const uint4*>(g_lut + b * LUTN)[t - 256];
    }
    if (t == 0) sgoff[GPB] = vn;
    __syncthreads();

    const size_t bo = (size_t)b * HW_TOTAL;
    const unsigned char* bytesBatch = g_bytes + (size_t)b * 32768;

    const int j1 = sv1 % vn;
    const int j2 = sv2 % vn;
    const int p1 = rank_select(j1, sgoff, slut, bytesBatch);
    const int p2 = rank_select(j2, sgoff, slut, bytesBatch);

    const float av = __ldcg(d3 + bo + p1);
    const float bv = __ldcg(d3 + bo + p2);
    const float diff = __ldcg(dp + bo + p1) - __ldcg(dp + bo + p2);

    float ls1 = 0.f, ls2 = 0.f;
    int lc1 = 0, lc2 = 0;
    if (av > bv + EPS_F) { ls1 = fmaxf(-diff, 0.f); lc1 = 1; }
    if (av < bv - EPS_F) { ls2 = fmaxf(diff, 0.f);  lc2 = 1; }

    #pragma unroll
    for (int o = 16; o; o >>= 1) {
        ls1 += __shfl_down_sync(0xFFFFFFFFu, ls1, o);
        ls2 += __shfl_down_sync(0xFFFFFFFFu, ls2, o);
        lc1 += __shfl_down_sync(0xFFFFFFFFu, lc1, o);
        lc2 += __shfl_down_sync(0xFFFFFFFFu, lc2, o);
    }
    if (lane == 0) { sf1[wid] = ls1; sf2[wid] = ls2; si1[wid] = lc1; si2[wid] = lc2; }
    __syncthreads();
    if (wid == 0) {
        float v1 = (lane < 16) ? sf1[lane] : 0.f;
        float v2 = (lane < 16) ? sf2[lane] : 0.f;
        int   i1r = (lane < 16) ? si1[lane] : 0;
        int   i2r = (lane < 16) ? si2[lane] : 0;
        #pragma unroll
        for (int o = 8; o; o >>= 1) {
            v1 += __shfl_down_sync(0xFFFFFFFFu, v1, o);
            v2 += __shfl_down_sync(0xFFFFFFFFu, v2, o);
            i1r += __shfl_down_sync(0xFFFFFFFFu, i1r, o);
            i2r += __shfl_down_sync(0xFFFFFFFFu, i2r, o);
        }
        if (lane == 0) {
            atomicAdd(&g_sum1, (double)v1);
            atomicAdd(&g_sum2, (double)v2);
            atomicAdd(&g_cnt1, i1r);
            atomicAdd(&g_cnt2, i2r);
        }
    }

    // last-block finalize
    __threadfence();
    __syncthreads();
    if (t == 0) {
        if (atomicAdd(&g_done2, 1) == SMP_BLOCKS - 1) {
            g_done2 = 0;
            double a1 = *(volatile double*)&g_sum1;
            double a2 = *(volatile double*)&g_sum2;
            int    n1 = *(volatile int*)&g_cnt1;
            int    n2 = *(volatile int*)&g_cnt2;
            out[0] = 0.5f * (float)(a1 / (double)n1 + a2 / (double)n2);
        }
    }
}

extern "C" void kernel_launch(void* const* d_in, const int* in_sizes, int n_in,
                              void* d_out, int out_size) {
    const float* d3   = (const float*)d_in[0];   // depth_3dmm
    const float* dp   = (const float*)d_in[1];   // depth_pigan
    const int*   mask = (const int*)d_in[2];
    const int*   s1   = (const int*)d_in[3];
    const int*   s2   = (const int*)d_in[4];

    k_count<<<CNT_BLOCKS, 512>>>(mask);
    k_prep<<<BATCH, 256>>>();
    k_sample<<<SMP_BLOCKS, 512>>>(d3, dp, s1, s2, (float*)d_out);
}

// round 13
// speedup vs baseline: 1.8163x; 1.0102x over previous
#include <cuda_runtime.h>
#include <cstdint>

// Problem constants (fixed by the reference)
#define HW_TOTAL (512 * 512)                  // 262144 pixels per batch image
#define BATCH 32
#define PSAMP 8192
#define NSAMP (BATCH * PSAMP)                 // 262144 samples
#define GPB 1024                              // 256-px groups per batch
#define LUTN 2048                             // rank->group LUT entries (gran 128)
#define EPS_F 1e-5f

#define CNT_BLOCKS 512                        // 16384 px per block = 1/16 batch
#define SMP_BLOCKS 256                        // 1024 samples per block
#define EPS_F 1e-5f

// -------- device scratch (static globals: no runtime allocation) --------
__device__ __align__(256) unsigned char g_bytes[(size_t)BATCH * GPB * 32]; // 1 MB packed mask
__device__ __align__(16)  unsigned short g_grpCnt[BATCH * GPB];            // 64 KB group counts
__device__ __align__(16)  int            g_grpOff[BATCH * GPB];            // 128 KB group offsets
__device__ __align__(16)  unsigned short g_lut[BATCH * LUTN];              // 128 KB rank->group
__device__ int      g_validNum[BATCH];
__device__ unsigned g_batchDone[BATCH];       // zero-init; self-resetting
__device__ double   g_sum1, g_sum2;
__device__ int      g_cnt1, g_cnt2;
__device__ unsigned g_done2;                  // zero-init; self-resetting

// ======== kernel 1: mask -> bitmask + counts; last block per batch preps ====
__global__ void __launch_bounds__(512) k_count(const int* __restrict__ mask) {
    const int t = threadIdx.x, lane = t & 31, wid = t >> 5;
    const int bid = blockIdx.x;
    const int b = bid >> 4;                    // 16 blocks per batch

    #pragma unroll 1
    for (int tile = 0; tile < 2; tile++) {
        const size_t basePx = (size_t)bid * 16384 +
                              (size_t)tile * 8192 + (size_t)t * 16;
        const int4* p = reinterpret_cast<const int4*>(mask + basePx);
        int4 v0 = __ldcs(p + 0);
        int4 v1 = __ldcs(p + 1);
        int4 v2 = __ldcs(p + 2);
        int4 v3 = __ldcs(p + 3);

        unsigned m16 =
              (unsigned)(v0.x != 0)       | (unsigned)(v0.y != 0) << 1
            | (unsigned)(v0.z != 0) << 2  | (unsigned)(v0.w != 0) << 3
            | (unsigned)(v1.x != 0) << 4  | (unsigned)(v1.y != 0) << 5
            | (unsigned)(v1.z != 0) << 6  | (unsigned)(v1.w != 0) << 7
            | (unsigned)(v2.x != 0) << 8  | (unsigned)(v2.y != 0) << 9
            | (unsigned)(v2.z != 0) << 10 | (unsigned)(v2.w != 0) << 11
            | (unsigned)(v3.x != 0) << 12 | (unsigned)(v3.y != 0) << 13
            | (unsigned)(v3.z != 0) << 14 | (unsigned)(v3.w != 0) << 15;

        reinterpret_cast<unsigned short*>(g_bytes)[bid * 1024 + tile * 512 + t] =
            (unsigned short)m16;

        const int c = __popc(m16);
        const unsigned hm = (lane < 16) ? 0x0000FFFFu : 0xFFFF0000u;
        const int gsum = __reduce_add_sync(hm, c);
        if ((lane & 15) == 0)
            g_grpCnt[bid * 64 + tile * 32 + (t >> 4)] = (unsigned short)gsum;
    }

    // ---- per-batch done counter: 16th block of batch b runs the prep ----
    __shared__ unsigned sPos;
    __threadfence();                           // release counts/bitmask
    if (t == 0) sPos = atomicAdd(&g_batchDone[b], 1u);
    __syncthreads();
    if (sPos != 15u) return;
    __threadfence();                           // acquire peers' stores

    if (t == 0) g_batchDone[b] = 0u;           // reset for next graph replay

    // ---- prep for batch b: scan 1024 group counts (2/thread) + LUT ----
    __shared__ int wtot[16];
    __shared__ int wexc[16];
    __shared__ int svn;

    ushort2 gc = reinterpret_cast<const ushort2*>(g_grpCnt + b * GPB)[t];
    const int c0 = gc.x, c1 = gc.y;
    const int s2c = c0 + c1;
    int inc = s2c;
    #pragma unroll
    for (int o = 1; o < 32; o <<= 1) {
        int v = __shfl_up_sync(0xFFFFFFFFu, inc, o);
        if (lane >= o) inc += v;
    }
    if (lane == 31) wtot[wid] = inc;
    __syncthreads();
    if (wid == 0 && lane < 16) {
        int v = wtot[lane];
        int i16 = v;
        #pragma unroll
        for (int o = 1; o < 16; o <<= 1) {
            int u = __shfl_up_sync(0xFFFFu, i16, o);
            if (lane >= o) i16 += u;
        }
        wexc[lane] = i16 - v;
        if (lane == 15) { svn = i16; g_validNum[b] = i16; }
    }
    __syncthreads();

    const int exc = wexc[wid] + (inc - s2c);
    int2 go2; go2.x = exc; go2.y = exc + c0;
    int* go = g_grpOff + b * GPB;
    reinterpret_cast<int2*>(go)[t] = go2;
    __syncthreads();

    unsigned short* lut = g_lut + b * LUTN;
    const int vn = svn;
    #pragma unroll
    for (int k = 0; k < 2; k++) {
        int g = t * 2 + k;
        int start = (k == 0) ? go2.x : go2.y;
        int end = (g == GPB - 1) ? vn : go[g + 1];
        for (int kk = (start + 127) >> 7; (kk << 7) < end; kk++)
            lut[kk] = (unsigned short)g;
    }

    if (b == 0 && t == 0) { g_sum1 = 0.0; g_sum2 = 0.0; g_cnt1 = 0; g_cnt2 = 0; }
}

// ======== select: rank -> pixel (smem offsets/LUT, L1-cached bit-words) ====
__device__ __forceinline__ int rank_select(int j, const int* sgoff,
                                           const unsigned short* slut,
                                           const unsigned char* bytesBatch) {
    int g = slut[j >> 7];
    while (sgoff[g + 1] <= j) g++;
    int r = j - sgoff[g];

    const ulonglong2* bp =
        reinterpret_cast<const ulonglong2*>(bytesBatch + (size_t)g * 32);
    ulonglong2 q0 = bp[0];
    ulonglong2 q1 = bp[1];

    unsigned long long w = q0.x; int wsel = 0;
    int q = __popcll(q0.x);
    if (r >= q) { r -= q; q = __popcll(q0.y);
        if (r >= q) { r -= q; q = __popcll(q1.x);
            if (r >= q) { r -= q; w = q1.y; wsel = 3; }
            else        {         w = q1.x; wsel = 2; } }
        else        {         w = q0.y; wsel = 1; } }
    unsigned lo = (unsigned)w; int pl = __popc(lo);
    int bit = (r < pl) ? (int)__fns(lo, 0, r + 1)
                       : 32 + (int)__fns((unsigned)(w >> 32), 0, r - pl + 1);
    return g * 256 + wsel * 64 + bit;
}

// ======== kernel 2: sample gather + reduce (2 samples/thread, 512 thr) =====
__global__ void __launch_bounds__(512) k_sample(const float* __restrict__ d3,
                                                const float* __restrict__ dp,
                                                const int* __restrict__ s1,
                                                const int* __restrict__ s2,
                                                float* __restrict__ out) {
    const int t = threadIdx.x, lane = t & 31, wid = t >> 5;
    const int b = blockIdx.x >> 3;                       // 8 blocks per batch
    const int iBase = b * PSAMP + (blockIdx.x & 7) * 1024;
    const int i0 = iBase + t;
    const int i1 = iBase + t + 512;

    // early independent loads (overlap with prologue)
    const int sv1a = __ldcg(s1 + i0);
    const int sv2a = __ldcg(s2 + i0);
    const int sv1b = __ldcg(s1 + i1);
    const int sv2b = __ldcg(s2 + i1);
    const int vn   = __ldg(&g_validNum[b]);

    __shared__ __align__(16) int            sgoff[GPB + 4];  // 4 KB + pad
    __shared__ __align__(16) unsigned short slut[LUTN];      // 4 KB
    __shared__ float sf1[16], sf2[16];
    __shared__ int   si1[16], si2[16];

    // prologue: 8 KB L2 -> smem (one 16B op per thread)
    if (t < 256) {
        reinterpret_cast<uint4*>(sgoff)[t] =
            reinterpret_cast<const uint4*>(g_grpOff + b * GPB)[t];
    } else {
        reinterpret_cast<uint4*>(slut)[t - 256] =
            reinterpret_cast<const uint4*>(g_lut + b * LUTN)[t - 256];
    }
    if (t == 0) sgoff[GPB] = vn;
    __syncthreads();

    const size_t bo = (size_t)b * HW_TOTAL;
    const unsigned char* bytesBatch = g_bytes + (size_t)b * 32768;

    const int j1a = sv1a % vn, j2a = sv2a % vn;
    const int j1b = sv1b % vn, j2b = sv2b % vn;

    const int p1a = rank_select(j1a, sgoff, slut, bytesBatch);
    const int p2a = rank_select(j2a, sgoff, slut, bytesBatch);
    const int p1b = rank_select(j1b, sgoff, slut, bytesBatch);
    const int p2b = rank_select(j2b, sgoff, slut, bytesBatch);

    const float a_a = __ldcg(d3 + bo + p1a);
    const float b_a = __ldcg(d3 + bo + p2a);
    const float a_b = __ldcg(d3 + bo + p1b);
    const float b_b = __ldcg(d3 + bo + p2b);
    const float df_a = __ldcg(dp + bo + p1a) - __ldcg(dp + bo + p2a);
    const float df_b = __ldcg(dp + bo + p1b) - __ldcg(dp + bo + p2b);

    float ls1 = 0.f, ls2 = 0.f;
    int lc1 = 0, lc2 = 0;
    if (a_a > b_a + EPS_F) { ls1 += fmaxf(-df_a, 0.f); lc1++; }
    if (a_a < b_a - EPS_F) { ls2 += fmaxf(df_a, 0.f);  lc2++; }
    if (a_b > b_b + EPS_F) { ls1 += fmaxf(-df_b, 0.f); lc1++; }
    if (a_b < b_b - EPS_F) { ls2 += fmaxf(df_b, 0.f);  lc2++; }

    #pragma unroll
    for (int o = 16; o; o >>= 1) {
        ls1 += __shfl_down_sync(0xFFFFFFFFu, ls1, o);
        ls2 += __shfl_down_sync(0xFFFFFFFFu, ls2, o);
        lc1 += __shfl_down_sync(0xFFFFFFFFu, lc1, o);
        lc2 += __shfl_down_sync(0xFFFFFFFFu, lc2, o);
    }
    if (lane == 0) { sf1[wid] = ls1; sf2[wid] = ls2; si1[wid] = lc1; si2[wid] = lc2; }
    __syncthreads();
    if (wid == 0) {
        float v1 = (lane < 16) ? sf1[lane] : 0.f;
        float v2 = (lane < 16) ? sf2[lane] : 0.f;
        int   i1r = (lane < 16) ? si1[lane] : 0;
        int   i2r = (lane < 16) ? si2[lane] : 0;
        #pragma unroll
        for (int o = 8; o; o >>= 1) {
            v1 += __shfl_down_sync(0xFFFFFFFFu, v1, o);
            v2 += __shfl_down_sync(0xFFFFFFFFu, v2, o);
            i1r += __shfl_down_sync(0xFFFFFFFFu, i1r, o);
            i2r += __shfl_down_sync(0xFFFFFFFFu, i2r, o);
        }
        if (lane == 0) {
            atomicAdd(&g_sum1, (double)v1);
            atomicAdd(&g_sum2, (double)v2);
            atomicAdd(&g_cnt1, i1r);
            atomicAdd(&g_cnt2, i2r);
        }
    }

    // last-block finalize
    __threadfence();
    __syncthreads();
    if (t == 0) {
        if (atomicAdd(&g_done2, 1) == SMP_BLOCKS - 1) {
            g_done2 = 0;
            double a1 = *(volatile double*)&g_sum1;
            double a2 = *(volatile double*)&g_sum2;
            int    n1 = *(volatile int*)&g_cnt1;
            int    n2 = *(volatile int*)&g_cnt2;
            out[0] = 0.5f * (float)(a1 / (double)n1 + a2 / (double)n2);
        }
    }
}

extern "C" void kernel_launch(void* const* d_in, const int* in_sizes, int n_in,
                              void* d_out, int out_size) {
    const float* d3   = (const float*)d_in[0];   // depth_3dmm
    const float* dp   = (const float*)d_in[1];   // depth_pigan
    const int*   mask = (const int*)d_in[2];
    const int*   s1   = (const int*)d_in[3];
    const int*   s2   = (const int*)d_in[4];

    k_count<<<CNT_BLOCKS, 512>>>(mask);
    k_sample<<<SMP_BLOCKS, 512>>>(d3, dp, s1, s2, (float*)d_out);
}